// round 12
// baseline (speedup 1.0000x reference)
#include <cuda_runtime.h>

// YOLO v1 loss (reference-bug-compatible):
//   predictions: [N, 49*30] f32  (per cell: 20 class, b1[x,y,w,h,c], b2[x,y,w,h,c])
//   targets:     [N, 49*25] f32  (per cell: 20 class, flag, box_rest[4])
//   tbox = targets[cell][20:25] -> (flag, bx, by, bw, bh); flag acts as "x" in IoU/xy.
//   obj  = (flag == 1.0f)
// out[0] = (sum obj*(coord+conf+cls) + 0.5*sum (1-obj)*(b1c^2+b2c^2)) / N
//
// Layout: per-thread AoS gathers at 120B/100B lane stride would cost ~30 L1tex
// wavefront replays per LDG (2.07 cyc/wf measured on B300) -> L1tex-bound at
// ~7x the DRAM floor. Instead each 128-thread block stages a 128-cell tile
// through smem with coalesced LDGs (pred as float2 — tile base is 8B-aligned;
// targets as float4 — tile base is 16B-aligned), predictions re-strided
// 30 -> 31 so the compute-phase LDS is bank-conflict-free.

#define NCLS       20
#define PRED_CH    30
#define PRED_PAD   31
#define TGT_CH     25
#define SS_CELLS   49
#define LAMBDA_COORD 5.0f
#define LAMBDA_NOOBJ 0.5f
#define IOU_EPS    1e-6f

#define TPB        128
#define TILE       128
#define MAX_BLOCKS 8192

__device__ float g_partials[MAX_BLOCKS];

__device__ __forceinline__ float iou_mid(float ax, float ay, float aw, float ah,
                                         float bx, float by, float bw, float bh) {
    float ax1 = ax - aw * 0.5f, ay1 = ay - ah * 0.5f;
    float ax2 = ax + aw * 0.5f, ay2 = ay + ah * 0.5f;
    float bx1 = bx - bw * 0.5f, by1 = by - bh * 0.5f;
    float bx2 = bx + bw * 0.5f, by2 = by + bh * 0.5f;
    float iw = fmaxf(fminf(ax2, bx2) - fmaxf(ax1, bx1), 0.0f);
    float ih = fmaxf(fminf(ay2, by2) - fmaxf(ay1, by1), 0.0f);
    float inter  = iw * ih;
    float area_a = fabsf((ax2 - ax1) * (ay2 - ay1));
    float area_b = fabsf((bx2 - bx1) * (by2 - by1));
    return inter / (area_a + area_b - inter + IOU_EPS);
}

__global__ void __launch_bounds__(TPB)
yolo_main(const float* __restrict__ pred, const float* __restrict__ tgt,
          int total_cells) {
    __shared__ float sp[TILE * PRED_PAD];   // 15872 B, stride 31 -> conflict-free LDS
    __shared__ float st[TILE * TGT_CH];     // 12800 B, stride 25 (odd) -> conflict-free LDS

    const int tid       = threadIdx.x;
    const int base_cell = blockIdx.x * TILE;

    // ---- stage predictions: coalesced float2 LDG (tile base 8B-aligned),
    //      re-stride 30 -> 31.  Each float2 stays inside one cell (even ch). ----
    {
        const float*  gp  = pred + (size_t)base_cell * PRED_CH;
        const float2* gp2 = reinterpret_cast<const float2*>(gp);
        const int limit = (total_cells - base_cell) * PRED_CH;
#pragma unroll 8
        for (int i4 = tid; i4 < TILE * PRED_CH / 2; i4 += TPB) {
            int i = i4 * 2;
            float2 v;
            if (i + 1 < limit) {
                v = gp2[i4];
            } else {                      // tail tile only (unused when cells % 128 == 0)
                v.x = (i     < limit) ? gp[i]     : 0.0f;
                v.y = (i + 1 < limit) ? gp[i + 1] : 0.0f;
            }
            unsigned c  = (unsigned)i / PRED_CH;
            unsigned ch = (unsigned)i - c * PRED_CH;     // even, ch+1 <= 29
            sp[c * PRED_PAD + ch]     = v.x;
            sp[c * PRED_PAD + ch + 1] = v.y;
        }
    }
    // ---- stage targets: coalesced float4 identity copy (tile base 16B-aligned) ----
    {
        const float* gt = tgt + (size_t)base_cell * TGT_CH;
        const int limit = (total_cells - base_cell) * TGT_CH;
        const float4* gt4 = reinterpret_cast<const float4*>(gt);
        float4* st4 = reinterpret_cast<float4*>(st);
#pragma unroll
        for (int i4 = tid; i4 < TILE * TGT_CH / 4; i4 += TPB) {
            int e = i4 * 4;
            if (e + 3 < limit) {
                st4[i4] = gt4[i4];
            } else {                      // tail tile only
                float4 v;
                v.x = (e + 0 < limit) ? gt[e + 0] : 0.0f;
                v.y = (e + 1 < limit) ? gt[e + 1] : 0.0f;
                v.z = (e + 2 < limit) ? gt[e + 2] : 0.0f;
                v.w = (e + 3 < limit) ? gt[e + 3] : 0.0f;
                st4[i4] = v;
            }
        }
    }
    __syncthreads();

    // ---- per-thread cell compute from smem (bank-conflict-free) ----
    float acc = 0.0f;
    const int cell = base_cell + tid;
    if (cell < total_cells) {
        const float* P = &sp[tid * PRED_PAD];
        const float* T = &st[tid * TGT_CH];

        float cls = 0.0f;
#pragma unroll
        for (int i = 0; i < NCLS; i++) {
            float d = P[i] - T[i];
            cls = fmaf(d, d, cls);
        }

        float b1x = P[20], b1y = P[21], b1w = P[22], b1h = P[23], b1c = P[24];
        float b2x = P[25], b2y = P[26], b2w = P[27], b2h = P[28], b2c = P[29];

        float tb0 = T[20];  // flag (reference uses it as the "x" coordinate)
        float tb1 = T[21], tb2 = T[22], tb3 = T[23], tb4 = T[24];

        float obj = (tb0 == 1.0f) ? 1.0f : 0.0f;

        float iou1 = iou_mid(b1x, b1y, b1w, b1h, tb0, tb1, tb2, tb3);
        float iou2 = iou_mid(b2x, b2y, b2w, b2h, tb0, tb1, tb2, tb3);

        bool sel = iou1 > iou2;                 // tie -> b2 (matches jnp.where)
        float rx = sel ? b1x : b2x;
        float ry = sel ? b1y : b2y;
        float rw = sel ? b1w : b2w;
        float rh = sel ? b1h : b2h;
        float rc = sel ? b1c : b2c;

        float dx = rx - tb0, dy = ry - tb1;
        float xy = dx * dx + dy * dy;
        float dw = sqrtf(rw) - sqrtf(tb2);
        float dh = sqrtf(rh) - sqrtf(tb3);
        float wh = dw * dw + dh * dh;
        float coord = LAMBDA_COORD * (xy + wh);
        float dc = rc - tb4;
        float conf = dc * dc;

        acc = obj * (coord + conf + cls)
            + LAMBDA_NOOBJ * (1.0f - obj) * (b1c * b1c + b2c * b2c);
    }

    // ---- deterministic block reduction (4 warps) ----
    int lane = tid & 31;
    int wid  = tid >> 5;
#pragma unroll
    for (int o = 16; o > 0; o >>= 1)
        acc += __shfl_down_sync(0xffffffffu, acc, o);

    __shared__ float sh[TPB / 32];
    if (lane == 0) sh[wid] = acc;
    __syncthreads();
    if (wid == 0) {
        float v = (lane < TPB / 32) ? sh[lane] : 0.0f;
#pragma unroll
        for (int o = 16; o > 0; o >>= 1)
            v += __shfl_down_sync(0xffffffffu, v, o);
        if (lane == 0) g_partials[blockIdx.x] = v;
    }
}

__global__ void __launch_bounds__(1024)
yolo_reduce(float* __restrict__ out, int nblocks, float inv_n) {
    float s = 0.0f;
    for (int i = threadIdx.x; i < nblocks; i += 1024)
        s += g_partials[i];

    int lane = threadIdx.x & 31;
    int wid  = threadIdx.x >> 5;
#pragma unroll
    for (int o = 16; o > 0; o >>= 1)
        s += __shfl_down_sync(0xffffffffu, s, o);

    __shared__ float sh[32];
    if (lane == 0) sh[wid] = s;
    __syncthreads();
    if (wid == 0) {
        float v = (lane < 32) ? sh[lane] : 0.0f;
#pragma unroll
        for (int o = 16; o > 0; o >>= 1)
            v += __shfl_down_sync(0xffffffffu, v, o);
        if (lane == 0) out[0] = v * inv_n;
    }
}

extern "C" void kernel_launch(void* const* d_in, const int* in_sizes, int n_in,
                              void* d_out, int out_size) {
    const float* pred = (const float*)d_in[0];
    const float* tgt  = (const float*)d_in[1];

    int total_cells = in_sizes[0] / PRED_CH;   // N * 49 = 802816 for N=16384
    int N           = total_cells / SS_CELLS;

    int grid = (total_cells + TILE - 1) / TILE;   // 6272 for N=16384
    if (grid > MAX_BLOCKS) grid = MAX_BLOCKS;

    yolo_main<<<grid, TPB>>>(pred, tgt, total_cells);
    yolo_reduce<<<1, 1024>>>((float*)d_out, grid, 1.0f / (float)N);
}